// round 2
// baseline (speedup 1.0000x reference)
#include <cuda_runtime.h>
#include <cuda_bf16.h>
#include <math.h>

// Problem dims (fixed by reference)
#define BATCH   64          // B*L = 4*16
#define NNODE   4096        // H
#define NFEAT   128         // W == nclass
#define NHID    256
#define BK      16

// Scratch: T = adj@x [64][4096][128]; A2 same shape. O reuses g_T.
// Static device arrays -> no allocation inside kernel_launch (guard-safe).
__device__ float g_T [(size_t)BATCH * NNODE * NFEAT];
__device__ float g_A2[(size_t)BATCH * NNODE * NFEAT];

// ---------------------------------------------------------------------------
// K1/K3: C[b][n][w] = sum_k adj[n][k] * X[b][k][w]
// adj [4096][4096], X [64][4096][128], C [64][4096][128].
// 128x128 tile per CTA (b = blockIdx.y), BK=16, 256 threads, 8x8 microtile,
// double-buffered shared memory with register prefetch.
// ---------------------------------------------------------------------------
__global__ void __launch_bounds__(256, 2)
gemm_adj(const float* __restrict__ adj,
         const float* __restrict__ X,
         float* __restrict__ C)
{
    __shared__ float As[2][BK][128];   // [buf][kk][n]  (adj tile, transposed)
    __shared__ float Xs[2][BK][128];   // [buf][kk][w]

    const int b  = blockIdx.y;
    const int n0 = blockIdx.x * 128;
    const float* __restrict__ Xb = X + (size_t)b * NNODE * NFEAT;
    float* __restrict__ Cb       = C + (size_t)b * NNODE * NFEAT + (size_t)n0 * NFEAT;

    const int tid  = threadIdx.x;
    const int warp = tid >> 5;
    const int lane = tid & 31;
    // warp grid 4(m) x 2(n); lane grid 4(m) x 8(n)
    const int rn = (warp >> 1) * 32 + (lane >> 3) * 8;   // 0..120
    const int rw = (warp & 1) * 64 + (lane & 7) * 8;     // 0..120

    // global-load indices
    const int la_n = tid >> 1;          // 0..127  (adj row within tile)
    const int la_k = (tid & 1) * 8;     // 0 or 8  (adj k offset; 2 float4 each)
    const int lx_k = tid >> 4;          // 0..15   (X k row)
    const int lx_w = (tid & 15) * 8;    // 0..120  (X w offset; 2 float4 each)

    const float* aptr = adj + (size_t)(n0 + la_n) * NNODE + la_k;
    const float* xptr = Xb + (size_t)lx_k * NFEAT + lx_w;

    float acc[8][8];
    #pragma unroll
    for (int i = 0; i < 8; i++)
        #pragma unroll
        for (int j = 0; j < 8; j++) acc[i][j] = 0.f;

    // ---- preload tile 0 into buffer 0 ----
    {
        float4 a0 = *(const float4*)(aptr);
        float4 a1 = *(const float4*)(aptr + 4);
        float4 x0 = *(const float4*)(xptr);
        float4 x1 = *(const float4*)(xptr + 4);
        As[0][la_k + 0][la_n] = a0.x;  As[0][la_k + 1][la_n] = a0.y;
        As[0][la_k + 2][la_n] = a0.z;  As[0][la_k + 3][la_n] = a0.w;
        As[0][la_k + 4][la_n] = a1.x;  As[0][la_k + 5][la_n] = a1.y;
        As[0][la_k + 6][la_n] = a1.z;  As[0][la_k + 7][la_n] = a1.w;
        *(float4*)&Xs[0][lx_k][lx_w]     = x0;
        *(float4*)&Xs[0][lx_k][lx_w + 4] = x1;
    }
    __syncthreads();

    int buf = 0;
    for (int k0 = BK; k0 < NNODE; k0 += BK) {
        // prefetch next tile into registers (overlaps with compute below)
        const float4 pa0 = *(const float4*)(aptr + k0);
        const float4 pa1 = *(const float4*)(aptr + k0 + 4);
        const float4 px0 = *(const float4*)(xptr + (size_t)k0 * NFEAT);
        const float4 px1 = *(const float4*)(xptr + (size_t)k0 * NFEAT + 4);

        // compute on current buffer
        #pragma unroll
        for (int kk = 0; kk < BK; kk++) {
            float a[8], xr[8];
            *(float4*)(a)      = *(const float4*)&As[buf][kk][rn];
            *(float4*)(a + 4)  = *(const float4*)&As[buf][kk][rn + 4];
            *(float4*)(xr)     = *(const float4*)&Xs[buf][kk][rw];
            *(float4*)(xr + 4) = *(const float4*)&Xs[buf][kk][rw + 4];
            #pragma unroll
            for (int i = 0; i < 8; i++)
                #pragma unroll
                for (int j = 0; j < 8; j++)
                    acc[i][j] = fmaf(a[i], xr[j], acc[i][j]);
        }

        // store prefetched tile into the other buffer
        const int nb = buf ^ 1;
        As[nb][la_k + 0][la_n] = pa0.x;  As[nb][la_k + 1][la_n] = pa0.y;
        As[nb][la_k + 2][la_n] = pa0.z;  As[nb][la_k + 3][la_n] = pa0.w;
        As[nb][la_k + 4][la_n] = pa1.x;  As[nb][la_k + 5][la_n] = pa1.y;
        As[nb][la_k + 6][la_n] = pa1.z;  As[nb][la_k + 7][la_n] = pa1.w;
        *(float4*)&Xs[nb][lx_k][lx_w]     = px0;
        *(float4*)&Xs[nb][lx_k][lx_w + 4] = px1;
        __syncthreads();
        buf = nb;
    }

    // final tile
    #pragma unroll
    for (int kk = 0; kk < BK; kk++) {
        float a[8], xr[8];
        *(float4*)(a)      = *(const float4*)&As[buf][kk][rn];
        *(float4*)(a + 4)  = *(const float4*)&As[buf][kk][rn + 4];
        *(float4*)(xr)     = *(const float4*)&Xs[buf][kk][rw];
        *(float4*)(xr + 4) = *(const float4*)&Xs[buf][kk][rw + 4];
        #pragma unroll
        for (int i = 0; i < 8; i++)
            #pragma unroll
            for (int j = 0; j < 8; j++)
                acc[i][j] = fmaf(a[i], xr[j], acc[i][j]);
    }

    #pragma unroll
    for (int i = 0; i < 8; i++) {
        *(float4*)(Cb + (size_t)(rn + i) * NFEAT + rw)     = *(float4*)&acc[i][0];
        *(float4*)(Cb + (size_t)(rn + i) * NFEAT + rw + 4) = *(float4*)&acc[i][4];
    }
}

// ---------------------------------------------------------------------------
// K2: per-row fused MLP. A2[r][:] = relu(T[r][:] @ W1 + b1) @ W2
// 256 threads handle 8 rows. W1/W2 (256 KB total) stay hot in L2.
// ---------------------------------------------------------------------------
__global__ void __launch_bounds__(256, 4)
mlp_fused(const float* __restrict__ T,
          const float* __restrict__ W1, const float* __restrict__ b1,
          const float* __restrict__ W2,
          float* __restrict__ A2)
{
    __shared__ float ts[8][NFEAT];    // 4 KB
    __shared__ float hs[8][NHID];     // 8 KB

    const int tid = threadIdx.x;
    const size_t row0 = (size_t)blockIdx.x * 8;
    const float* src = T + row0 * NFEAT;

    // load 8 rows x 128 floats = 256 float4
    ((float4*)&ts[0][0])[tid] = ((const float4*)src)[tid];
    __syncthreads();

    // stage 1: thread j == tid computes h[r][j] for all 8 rows
    float acc[8];
    const float bias = b1[tid];
    #pragma unroll
    for (int r = 0; r < 8; r++) acc[r] = bias;
    #pragma unroll 4
    for (int i = 0; i < NFEAT; i++) {
        const float w1 = W1[(size_t)i * NHID + tid];
        #pragma unroll
        for (int r = 0; r < 8; r++) acc[r] = fmaf(ts[r][i], w1, acc[r]);
    }
    #pragma unroll
    for (int r = 0; r < 8; r++) hs[r][tid] = fmaxf(acc[r], 0.f);
    __syncthreads();

    // stage 2: thread -> w = tid%128, rows {rb, rb+2, rb+4, rb+6}
    const int w  = tid & 127;
    const int rb = tid >> 7;           // 0 or 1
    float o0 = 0.f, o1 = 0.f, o2 = 0.f, o3 = 0.f;
    #pragma unroll 4
    for (int j = 0; j < NHID; j++) {
        const float w2 = W2[(size_t)j * NFEAT + w];
        o0 = fmaf(hs[rb + 0][j], w2, o0);
        o1 = fmaf(hs[rb + 2][j], w2, o1);
        o2 = fmaf(hs[rb + 4][j], w2, o2);
        o3 = fmaf(hs[rb + 6][j], w2, o3);
    }
    float* dst = A2 + row0 * NFEAT;
    dst[(size_t)(rb + 0) * NFEAT + w] = o0;
    dst[(size_t)(rb + 2) * NFEAT + w] = o1;
    dst[(size_t)(rb + 4) * NFEAT + w] = o2;
    dst[(size_t)(rb + 6) * NFEAT + w] = o3;
}

// ---------------------------------------------------------------------------
// K4: out = log_softmax(O + b2, axis=-1). One warp per row of 128.
// ---------------------------------------------------------------------------
__global__ void __launch_bounds__(256)
logsoftmax_k(const float* __restrict__ O,
             const float* __restrict__ b2,
             float* __restrict__ out)
{
    const int lane = threadIdx.x & 31;
    const size_t row = ((size_t)blockIdx.x * blockDim.x + threadIdx.x) >> 5;

    const float4 t  = ((const float4*)(O + row * NFEAT))[lane];
    const float4 bb = ((const float4*)b2)[lane];
    float v0 = t.x + bb.x, v1 = t.y + bb.y, v2 = t.z + bb.z, v3 = t.w + bb.w;

    float m = fmaxf(fmaxf(v0, v1), fmaxf(v2, v3));
    #pragma unroll
    for (int off = 16; off > 0; off >>= 1)
        m = fmaxf(m, __shfl_xor_sync(0xFFFFFFFFu, m, off));

    float s = expf(v0 - m) + expf(v1 - m) + expf(v2 - m) + expf(v3 - m);
    #pragma unroll
    for (int off = 16; off > 0; off >>= 1)
        s += __shfl_xor_sync(0xFFFFFFFFu, s, off);

    const float lse = m + logf(s);
    float4 o;
    o.x = v0 - lse; o.y = v1 - lse; o.z = v2 - lse; o.w = v3 - lse;
    ((float4*)(out + row * NFEAT))[lane] = o;
}

// ---------------------------------------------------------------------------
// Inputs (metadata order): x, adj, W1, b1, W2, b2. Output: float32 [4,16,4096,128].
// ---------------------------------------------------------------------------
extern "C" void kernel_launch(void* const* d_in, const int* in_sizes, int n_in,
                              void* d_out, int out_size)
{
    const float* x   = (const float*)d_in[0];
    const float* adj = (const float*)d_in[1];
    const float* W1  = (const float*)d_in[2];
    const float* b1  = (const float*)d_in[3];
    const float* W2  = (const float*)d_in[4];
    const float* b2  = (const float*)d_in[5];
    float* out = (float*)d_out;

    float *pT = nullptr, *pA2 = nullptr;
    cudaGetSymbolAddress((void**)&pT,  g_T);
    cudaGetSymbolAddress((void**)&pA2, g_A2);

    const dim3 ggrid(NNODE / 128, BATCH);          // 32 x 64
    const int  nrows = BATCH * NNODE;              // 262144

    // K1: T = adj @ x
    gemm_adj<<<ggrid, 256>>>(adj, x, pT);
    // K2: A2 = relu(T@W1 + b1) @ W2
    mlp_fused<<<nrows / 8, 256>>>(pT, W1, b1, W2, pA2);
    // K3: O = adj @ A2   (reuse g_T as O)
    gemm_adj<<<ggrid, 256>>>(adj, pA2, pT);
    // K4: out = log_softmax(O + b2)
    logsoftmax_k<<<nrows / 8, 256>>>(pT, b2, out);

    (void)in_sizes; (void)n_in; (void)out_size;
}

// round 5
// speedup vs baseline: 2.1607x; 2.1607x over previous
#include <cuda_runtime.h>
#include <cuda_bf16.h>
#include <math.h>
#include <stdint.h>

// Problem dims (fixed by reference)
#define BATCH   64          // B*L
#define NNODE   4096        // H
#define NFEAT   128         // W == nclass
#define NHID    256

// ---------------------------------------------------------------------------
// Static device scratch (no allocations allowed)
// ---------------------------------------------------------------------------
__device__ __nv_bfloat16 g_adj_hi[(size_t)NNODE * NNODE];          // 32 MB
__device__ __nv_bfloat16 g_adj_lo[(size_t)NNODE * NNODE];          // 32 MB
__device__ __nv_bfloat16 g_XT_hi[(size_t)BATCH * NFEAT * NNODE];   // 64 MB  [b][w][k]
__device__ __nv_bfloat16 g_XT_lo[(size_t)BATCH * NFEAT * NNODE];   // 64 MB
__device__ float         g_T   [(size_t)BATCH * NNODE * NFEAT];    // 128 MB

// ---------------------------------------------------------------------------
// PTX helpers (all sm_80-era: ldmatrix / mma.sync / cp.async)
// ---------------------------------------------------------------------------
__device__ __forceinline__ uint32_t smem_u32(const void* p) {
    uint32_t a;
    asm("{ .reg .u64 t; cvta.to.shared.u64 t, %1; cvt.u32.u64 %0, t; }" : "=r"(a) : "l"(p));
    return a;
}

#define LDSM4(r, a)                                                                 \
    asm volatile("ldmatrix.sync.aligned.m8n8.x4.shared.b16 {%0,%1,%2,%3}, [%4];"    \
        : "=r"((r)[0]), "=r"((r)[1]), "=r"((r)[2]), "=r"((r)[3]) : "r"(a))

#define LDSM2(r, a)                                                                 \
    asm volatile("ldmatrix.sync.aligned.m8n8.x2.shared.b16 {%0,%1}, [%2];"          \
        : "=r"((r)[0]), "=r"((r)[1]) : "r"(a))

#define MMA_BF16(c, a, bb)                                                          \
    asm volatile("mma.sync.aligned.m16n8k16.row.col.f32.bf16.bf16.f32 "             \
        "{%0,%1,%2,%3}, {%4,%5,%6,%7}, {%8,%9}, {%0,%1,%2,%3};"                     \
        : "+f"((c)[0]), "+f"((c)[1]), "+f"((c)[2]), "+f"((c)[3])                    \
        : "r"((a)[0]), "r"((a)[1]), "r"((a)[2]), "r"((a)[3]),                       \
          "r"((bb)[0]), "r"((bb)[1]))

#define CP16(dst, src) asm volatile("cp.async.cg.shared.global [%0], [%1], 16;" :: "r"(dst), "l"(src) : "memory")
#define CP_COMMIT()    asm volatile("cp.async.commit_group;" ::: "memory")
#define CP_WAIT1()     asm volatile("cp.async.wait_group 1;" ::: "memory")
#define CP_WAIT0()     asm volatile("cp.async.wait_group 0;" ::: "memory")

// ---------------------------------------------------------------------------
// adj fp32 -> bf16 hi/lo split (runs every call; deterministic)
// ---------------------------------------------------------------------------
__global__ void __launch_bounds__(256)
convert_adj(const float* __restrict__ adj,
            __nv_bfloat16* __restrict__ hi, __nv_bfloat16* __restrict__ lo)
{
    const size_t i = ((size_t)blockIdx.x * 256 + threadIdx.x) * 4;
    float4 a = *(const float4*)(adj + i);
    __nv_bfloat16 h[4], l[4];
    float v[4] = {a.x, a.y, a.z, a.w};
    #pragma unroll
    for (int j = 0; j < 4; j++) {
        h[j] = __float2bfloat16_rn(v[j]);
        l[j] = __float2bfloat16_rn(v[j] - __bfloat162float(h[j]));
    }
    *(uint2*)(hi + i) = *(uint2*)h;
    *(uint2*)(lo + i) = *(uint2*)l;
}

// ---------------------------------------------------------------------------
// x [b][n][w] fp32 -> XT hi/lo [b][w][n] bf16  (transpose + split)
// ---------------------------------------------------------------------------
__global__ void __launch_bounds__(256)
transpose_conv(const float* __restrict__ x,
               __nv_bfloat16* __restrict__ XTh, __nv_bfloat16* __restrict__ XTl)
{
    __shared__ float t[32][33];
    const int tx = threadIdx.x, ty = threadIdx.y;       // 32 x 8
    const int n0 = blockIdx.x * 32, w0 = blockIdx.y * 32, b = blockIdx.z;
    #pragma unroll
    for (int j = 0; j < 4; j++) {
        int n = n0 + ty + j * 8;
        t[ty + j * 8][tx] = x[((size_t)b * NNODE + n) * NFEAT + w0 + tx];
    }
    __syncthreads();
    #pragma unroll
    for (int j = 0; j < 4; j++) {
        int w = w0 + ty + j * 8;
        float v = t[tx][ty + j * 8];
        __nv_bfloat16 h = __float2bfloat16_rn(v);
        __nv_bfloat16 l = __float2bfloat16_rn(v - __bfloat162float(h));
        size_t o = ((size_t)b * NFEAT + w) * NNODE + n0 + tx;
        XTh[o] = h; XTl[o] = l;
    }
}

// ---------------------------------------------------------------------------
// HMMA GEMM: C[b][n][w] = sum_k adj[n][k] * X[b][k][w]
// A = adj (hi/lo, n-rows K-major), B = XT[b] (hi/lo, w-rows K-major).
// CTA 128x128, KC=64 chunks, 2-stage cp.async double buffer.
// 3-term bf16 split: hh + hl + lh into one fp32 accumulator.
// Warp grid 2(m) x 4(n); warp tile 64x32; mma m16n8k16.
// ---------------------------------------------------------------------------
#define KC       64
#define NSTAGE   (NNODE / KC)              // 64
#define ROW_B    144                       // 128B data + 16B pad
#define TILE_B   (128 * ROW_B)             // 18432 B
#define STAGE_B  (4 * TILE_B)              // 73728 B
#define SM_TOTAL (2 * STAGE_B)             // 147456 B

__global__ void __launch_bounds__(256, 1)
gemm_mma(const __nv_bfloat16* __restrict__ adj_hi,
         const __nv_bfloat16* __restrict__ adj_lo,
         const __nv_bfloat16* __restrict__ XTh,
         const __nv_bfloat16* __restrict__ XTl,
         float* __restrict__ C)
{
    extern __shared__ __align__(16) char smem[];
    const uint32_t sb = smem_u32(smem);
    const int tid  = threadIdx.x;
    const int wid  = tid >> 5, lane = tid & 31;
    const int wm   = wid & 1;              // 0..1  (64-row m group)
    const int wn   = wid >> 1;             // 0..3  (32-col n group)
    const int n0 = blockIdx.x * 128, b = blockIdx.y;

    // ---- cp.async load plan: 4096 x 16B chunks / 256 threads = 16 each ----
    const __nv_bfloat16* tbase[4] = {
        adj_hi + (size_t)n0 * NNODE, adj_lo + (size_t)n0 * NNODE,
        XTh + (size_t)b * NFEAT * NNODE, XTl + (size_t)b * NFEAT * NNODE };
    const __nv_bfloat16* src[16];
    uint32_t dst_off[16];
    #pragma unroll
    for (int j = 0; j < 16; j++) {
        int c    = j * 256 + tid;
        int tile = c >> 10;                // 1024 chunks per 128x64 tile
        int idx  = c & 1023;
        int row  = idx >> 3;
        int c16  = idx & 7;
        src[j]     = tbase[tile] + (size_t)row * NNODE + c16 * 8;
        dst_off[j] = tile * TILE_B + row * ROW_B + c16 * 16;
    }

    // ---- ldmatrix lane addresses (byte offsets within a stage) ----
    // A frag (m16k16): lanes 0-7 m0-7/k0, 8-15 m8-15/k0, 16-23 m0-7/k8, 24-31 m8-15/k8
    const uint32_t offA = (uint32_t)(wm * 64 + (lane & 15)) * ROW_B + (lane >> 4) * 16;
    // B frag (n8k16): lanes 0-7 n0-7/k0, 8-15 n0-7/k8
    const uint32_t offB = (uint32_t)(wn * 32 + (lane & 7)) * ROW_B + ((lane >> 3) & 1) * 16;

    float acc[4][4][4];
    #pragma unroll
    for (int mi = 0; mi < 4; mi++)
        #pragma unroll
        for (int ni = 0; ni < 4; ni++)
            #pragma unroll
            for (int e = 0; e < 4; e++) acc[mi][ni][e] = 0.f;

    // preload stage 0 into buffer 0
    #pragma unroll
    for (int j = 0; j < 16; j++) CP16(sb + dst_off[j], src[j]);
    CP_COMMIT();

    for (int i = 0; i < NSTAGE; i++) {
        const int buf = i & 1;
        if (i < NSTAGE - 1) {
            const uint32_t dbase = sb + (buf ^ 1) * STAGE_B;
            const int koff = (i + 1) * KC;
            #pragma unroll
            for (int j = 0; j < 16; j++) CP16(dbase + dst_off[j], src[j] + koff);
            CP_COMMIT();
            CP_WAIT1();
        } else {
            CP_WAIT0();
        }
        __syncthreads();

        const uint32_t s = sb + buf * STAGE_B;
        #pragma unroll
        for (int ks = 0; ks < 4; ks++) {
            uint32_t ah[4][4], al[4][4];
            #pragma unroll
            for (int mi = 0; mi < 4; mi++) {
                const uint32_t a = s + offA + mi * (16 * ROW_B) + ks * 32;
                LDSM4(ah[mi], a);
                LDSM4(al[mi], a + TILE_B);
            }
            uint32_t bh[4][2], bl[4][2];
            #pragma unroll
            for (int ni = 0; ni < 4; ni++) {
                const uint32_t a = s + 2 * TILE_B + offB + ni * (8 * ROW_B) + ks * 32;
                LDSM2(bh[ni], a);
                LDSM2(bl[ni], a + TILE_B);
            }
            #pragma unroll
            for (int mi = 0; mi < 4; mi++)
                #pragma unroll
                for (int ni = 0; ni < 4; ni++) {
                    MMA_BF16(acc[mi][ni], ah[mi], bh[ni]);
                    MMA_BF16(acc[mi][ni], ah[mi], bl[ni]);
                    MMA_BF16(acc[mi][ni], al[mi], bh[ni]);
                }
        }
        __syncthreads();   // protect buf before it is refilled next iteration
    }

    // ---- epilogue: registers -> C (row-major fp32) ----
    // acc frag: c0,c1 -> row m=lane/4, cols (lane%4)*2(+1); c2,c3 -> row m+8
    const int mrow = wm * 64 + (lane >> 2);
    const int ncol = wn * 32 + (lane & 3) * 2;
    float* Cb = C + ((size_t)b * NNODE + n0) * NFEAT;
    #pragma unroll
    for (int mi = 0; mi < 4; mi++) {
        #pragma unroll
        for (int ni = 0; ni < 4; ni++) {
            float* p0 = Cb + (size_t)(mrow + mi * 16) * NFEAT + ncol + ni * 8;
            float* p1 = p0 + 8 * NFEAT;
            *(float2*)p0 = make_float2(acc[mi][ni][0], acc[mi][ni][1]);
            *(float2*)p1 = make_float2(acc[mi][ni][2], acc[mi][ni][3]);
        }
    }
}

// ---------------------------------------------------------------------------
// K2: fused MLP; writes output transposed + bf16-split into XT buffers.
// A2T[b][w][n] = relu(T[row][:] @ W1 + b1) @ W2 , row = b*4096+n
// ---------------------------------------------------------------------------
__global__ void __launch_bounds__(256, 4)
mlp_fused(const float* __restrict__ T,
          const float* __restrict__ W1, const float* __restrict__ b1,
          const float* __restrict__ W2,
          __nv_bfloat16* __restrict__ XTh, __nv_bfloat16* __restrict__ XTl)
{
    __shared__ float ts[8][NFEAT];
    __shared__ float hs[8][NHID];
    __shared__ float os[8][NFEAT];

    const int tid = threadIdx.x;
    const size_t row0 = (size_t)blockIdx.x * 8;
    const int b     = (int)(row0 >> 12);
    const int nbase = (int)(row0 & 4095);

    ((float4*)&ts[0][0])[tid] = ((const float4*)(T + row0 * NFEAT))[tid];
    __syncthreads();

    // stage 1: thread j == tid computes h[r][j]
    float acc[8];
    const float bias = b1[tid];
    #pragma unroll
    for (int r = 0; r < 8; r++) acc[r] = bias;
    #pragma unroll 4
    for (int i = 0; i < NFEAT; i++) {
        const float w1 = W1[(size_t)i * NHID + tid];
        #pragma unroll
        for (int r = 0; r < 8; r++) acc[r] = fmaf(ts[r][i], w1, acc[r]);
    }
    #pragma unroll
    for (int r = 0; r < 8; r++) hs[r][tid] = fmaxf(acc[r], 0.f);
    __syncthreads();

    // stage 2
    const int w  = tid & 127;
    const int rb = tid >> 7;
    float o0 = 0.f, o1 = 0.f, o2 = 0.f, o3 = 0.f;
    #pragma unroll 4
    for (int j = 0; j < NHID; j++) {
        const float w2 = W2[(size_t)j * NFEAT + w];
        o0 = fmaf(hs[rb + 0][j], w2, o0);
        o1 = fmaf(hs[rb + 2][j], w2, o1);
        o2 = fmaf(hs[rb + 4][j], w2, o2);
        o3 = fmaf(hs[rb + 6][j], w2, o3);
    }
    os[rb + 0][w] = o0; os[rb + 2][w] = o1;
    os[rb + 4][w] = o2; os[rb + 6][w] = o3;
    __syncthreads();

    // transposed split store: thread -> (w2, hi/lo), 8 n-values = 16B
    const int w2   = tid & 127;
    const int half = tid >> 7;
    unsigned short pk[8];
    #pragma unroll
    for (int r = 0; r < 8; r++) {
        float v = os[r][w2];
        __nv_bfloat16 h = __float2bfloat16_rn(v);
        if (half == 0) pk[r] = __bfloat16_as_ushort(h);
        else           pk[r] = __bfloat16_as_ushort(__float2bfloat16_rn(v - __bfloat162float(h)));
    }
    __nv_bfloat16* dst = (half == 0 ? XTh : XTl) + ((size_t)b * NFEAT + w2) * NNODE + nbase;
    *(uint4*)dst = *(uint4*)pk;
}

// ---------------------------------------------------------------------------
// K4: out = log_softmax(O + b2). One warp per row.
// ---------------------------------------------------------------------------
__global__ void __launch_bounds__(256)
logsoftmax_k(const float* __restrict__ O,
             const float* __restrict__ b2,
             float* __restrict__ out)
{
    const int lane = threadIdx.x & 31;
    const size_t row = ((size_t)blockIdx.x * blockDim.x + threadIdx.x) >> 5;

    const float4 t  = ((const float4*)(O + row * NFEAT))[lane];
    const float4 bb = ((const float4*)b2)[lane];
    float v0 = t.x + bb.x, v1 = t.y + bb.y, v2 = t.z + bb.z, v3 = t.w + bb.w;

    float m = fmaxf(fmaxf(v0, v1), fmaxf(v2, v3));
    #pragma unroll
    for (int off = 16; off > 0; off >>= 1)
        m = fmaxf(m, __shfl_xor_sync(0xFFFFFFFFu, m, off));

    float s = expf(v0 - m) + expf(v1 - m) + expf(v2 - m) + expf(v3 - m);
    #pragma unroll
    for (int off = 16; off > 0; off >>= 1)
        s += __shfl_xor_sync(0xFFFFFFFFu, s, off);

    const float lse = m + logf(s);
    float4 o;
    o.x = v0 - lse; o.y = v1 - lse; o.z = v2 - lse; o.w = v3 - lse;
    ((float4*)(out + row * NFEAT))[lane] = o;
}

// ---------------------------------------------------------------------------
// Launch: convert adj, transpose-convert x, GEMM1, MLP(->XT), GEMM2, softmax
// ---------------------------------------------------------------------------
extern "C" void kernel_launch(void* const* d_in, const int* in_sizes, int n_in,
                              void* d_out, int out_size)
{
    const float* x   = (const float*)d_in[0];
    const float* adj = (const float*)d_in[1];
    const float* W1  = (const float*)d_in[2];
    const float* b1  = (const float*)d_in[3];
    const float* W2  = (const float*)d_in[4];
    const float* b2  = (const float*)d_in[5];
    float* out = (float*)d_out;

    __nv_bfloat16 *pAh, *pAl, *pXh, *pXl; float* pT;
    cudaGetSymbolAddress((void**)&pAh, g_adj_hi);
    cudaGetSymbolAddress((void**)&pAl, g_adj_lo);
    cudaGetSymbolAddress((void**)&pXh, g_XT_hi);
    cudaGetSymbolAddress((void**)&pXl, g_XT_lo);
    cudaGetSymbolAddress((void**)&pT,  g_T);

    cudaFuncSetAttribute(gemm_mma, cudaFuncAttributeMaxDynamicSharedMemorySize, SM_TOTAL);

    // preprocessing
    convert_adj<<<(NNODE * (size_t)NNODE) / (256 * 4), 256>>>(adj, pAh, pAl);
    transpose_conv<<<dim3(NNODE / 32, NFEAT / 32, BATCH), dim3(32, 8)>>>(x, pXh, pXl);

    const dim3 ggrid(NNODE / 128, BATCH);    // 32 x 64
    const int  nrows = BATCH * NNODE;        // 262144

    // K1: T = adj @ x
    gemm_mma<<<ggrid, 256, SM_TOTAL>>>(pAh, pAl, pXh, pXl, pT);
    // K2: XT <- split(transpose(relu(T@W1+b1)@W2))
    mlp_fused<<<nrows / 8, 256>>>(pT, W1, b1, W2, pXh, pXl);
    // K3: O = adj @ A2  (reuse g_T)
    gemm_mma<<<ggrid, 256, SM_TOTAL>>>(pAh, pAl, pXh, pXl, pT);
    // K4
    logsoftmax_k<<<nrows / 8, 256>>>(pT, b2, out);

    (void)in_sizes; (void)n_in; (void)out_size;
}

// round 7
// speedup vs baseline: 3.3641x; 1.5569x over previous
#include <cuda_runtime.h>
#include <cuda_bf16.h>
#include <math.h>
#include <stdint.h>

// Problem dims (fixed by reference)
#define BATCH   64          // B*L
#define NNODE   4096        // H
#define NFEAT   128         // W == nclass
#define NHID    256

// ---------------------------------------------------------------------------
// Static device scratch (no allocations allowed)
// ---------------------------------------------------------------------------
__device__ int8_t g_A1 [(size_t)NNODE * NNODE];                  // adj level-1, 16 MB
__device__ int8_t g_A2q[(size_t)NNODE * NNODE];                  // adj level-2, 16 MB
__device__ int8_t g_B1 [(size_t)BATCH * NFEAT * NNODE];          // B level-1 [b][w][k], 32 MB
__device__ int8_t g_B2q[(size_t)BATCH * NFEAT * NNODE];          // B level-2, 32 MB
__device__ float  g_T  [(size_t)BATCH * NNODE * NFEAT];          // 128 MB
__device__ float  g_A2T[(size_t)BATCH * NFEAT * NNODE];          // MLP out transposed, 128 MB
__device__ unsigned g_scal[3];                                   // absmax: adj, x, mlp

// ---------------------------------------------------------------------------
// PTX helpers (sm_80-era: ldmatrix / mma.sync s8 / cp.async)
// ---------------------------------------------------------------------------
__device__ __forceinline__ uint32_t smem_u32(const void* p) {
    uint32_t a;
    asm("{ .reg .u64 t; cvta.to.shared.u64 t, %1; cvt.u32.u64 %0, t; }" : "=r"(a) : "l"(p));
    return a;
}

#define LDSM4(r, a)                                                                 \
    asm volatile("ldmatrix.sync.aligned.m8n8.x4.shared.b16 {%0,%1,%2,%3}, [%4];"    \
        : "=r"((r)[0]), "=r"((r)[1]), "=r"((r)[2]), "=r"((r)[3]) : "r"(a))

#define LDSM2(r, a)                                                                 \
    asm volatile("ldmatrix.sync.aligned.m8n8.x2.shared.b16 {%0,%1}, [%2];"          \
        : "=r"((r)[0]), "=r"((r)[1]) : "r"(a))

#define MMA_S8(c, a, bb)                                                            \
    asm volatile("mma.sync.aligned.m16n8k32.row.col.s32.s8.s8.s32 "                 \
        "{%0,%1,%2,%3}, {%4,%5,%6,%7}, {%8,%9}, {%0,%1,%2,%3};"                     \
        : "+r"((c)[0]), "+r"((c)[1]), "+r"((c)[2]), "+r"((c)[3])                    \
        : "r"((a)[0]), "r"((a)[1]), "r"((a)[2]), "r"((a)[3]),                       \
          "r"((bb)[0]), "r"((bb)[1]))

#define CP16(dst, src) asm volatile("cp.async.cg.shared.global [%0], [%1], 16;" :: "r"(dst), "l"(src) : "memory")
#define CP_COMMIT()    asm volatile("cp.async.commit_group;" ::: "memory")
#define CP_WAIT1()     asm volatile("cp.async.wait_group 1;" ::: "memory")
#define CP_WAIT0()     asm volatile("cp.async.wait_group 0;" ::: "memory")

// two-level symmetric quantization: v ~= (max/127) * (q1 + q2/256)
__device__ __forceinline__ void q2lvl(float v, float inv, int& o1, int& o2) {
    float q  = v * inv;
    float r1 = rintf(q);
    r1 = fminf(127.f, fmaxf(-127.f, r1));
    float r2 = rintf((q - r1) * 256.f);
    r2 = fminf(127.f, fmaxf(-127.f, r2));
    o1 = (int)r1; o2 = (int)r2;
}

// ---------------------------------------------------------------------------
// tiny kernels: scalar reset, abs-max reduce
// ---------------------------------------------------------------------------
__global__ void zero_scal(unsigned* s) { s[0] = 0u; s[1] = 0u; s[2] = 0u; }

__global__ void __launch_bounds__(256)
rmax4(const float4* __restrict__ p, int n4, unsigned* out)
{
    float m = 0.f;
    for (int i = blockIdx.x * blockDim.x + threadIdx.x; i < n4; i += gridDim.x * blockDim.x) {
        float4 v = p[i];
        m = fmaxf(m, fmaxf(fmaxf(fabsf(v.x), fabsf(v.y)), fmaxf(fabsf(v.z), fabsf(v.w))));
    }
    #pragma unroll
    for (int o = 16; o > 0; o >>= 1) m = fmaxf(m, __shfl_xor_sync(0xFFFFFFFFu, m, o));
    __shared__ float red[8];
    if ((threadIdx.x & 31) == 0) red[threadIdx.x >> 5] = m;
    __syncthreads();
    if (threadIdx.x == 0) {
        float b = red[0];
        #pragma unroll
        for (int i = 1; i < 8; i++) b = fmaxf(b, red[i]);
        atomicMax(out, __float_as_uint(b));
    }
}

// ---------------------------------------------------------------------------
// pointwise 2-level quantize (adj, and MLP output which is already transposed)
// ---------------------------------------------------------------------------
__global__ void __launch_bounds__(256)
quant_pt(const float* __restrict__ src, int8_t* __restrict__ d1,
         int8_t* __restrict__ d2, const unsigned* __restrict__ mx)
{
    const float inv = 127.f / fmaxf(__uint_as_float(*mx), 1e-30f);
    const size_t i = ((size_t)blockIdx.x * 256 + threadIdx.x) * 4;
    float4 v = *(const float4*)(src + i);
    int a1, a2, b1, b2, c1, c2, e1, e2;
    q2lvl(v.x, inv, a1, a2); q2lvl(v.y, inv, b1, b2);
    q2lvl(v.z, inv, c1, c2); q2lvl(v.w, inv, e1, e2);
    *(char4*)(d1 + i) = make_char4((char)a1, (char)b1, (char)c1, (char)e1);
    *(char4*)(d2 + i) = make_char4((char)a2, (char)b2, (char)c2, (char)e2);
}

// ---------------------------------------------------------------------------
// x [b][n][w] fp32 -> int8x2 transposed [b][w][n]
// ---------------------------------------------------------------------------
__global__ void __launch_bounds__(256)
quant_xT(const float* __restrict__ x, int8_t* __restrict__ d1,
         int8_t* __restrict__ d2, const unsigned* __restrict__ mx)
{
    __shared__ float t[32][33];
    const float inv = 127.f / fmaxf(__uint_as_float(*mx), 1e-30f);
    const int tx = threadIdx.x, ty = threadIdx.y;       // 32 x 8
    const int n0 = blockIdx.x * 32, w0 = blockIdx.y * 32, b = blockIdx.z;
    #pragma unroll
    for (int j = 0; j < 4; j++) {
        int n = n0 + ty + j * 8;
        t[ty + j * 8][tx] = x[((size_t)b * NNODE + n) * NFEAT + w0 + tx];
    }
    __syncthreads();
    #pragma unroll
    for (int j = 0; j < 4; j++) {
        int w = w0 + ty + j * 8;
        int q1, q2;
        q2lvl(t[tx][ty + j * 8], inv, q1, q2);
        size_t o = ((size_t)b * NFEAT + w) * NNODE + n0 + tx;
        d1[o] = (int8_t)q1; d2[o] = (int8_t)q2;
    }
}

// ---------------------------------------------------------------------------
// int8 two-level GEMM: C[b][n][w] = sum_k adj[n][k] * X[b][k][w]
// A = adj (levels 1/2, n-rows K-major int8), B = XT[b] (levels 1/2, w-rows K-major).
// CTA 128x128, KC=128 int8 per stage (128B rows), 2-stage cp.async.
// P1 = a1*b1 ; P2 = a1*b2 + a2*b1 ; C = s*(P1 + P2/256), s = maxA*maxB/127^2.
// Warp grid 2(m) x 4(n); warp tile 64x32; mma m16n8k32.s8.
// ---------------------------------------------------------------------------
#define KC       128                       // int8 elements per k-stage
#define NSTAGE   (NNODE / KC)              // 32
#define ROW_B    144                       // 128B data + 16B pad
#define TILE_B   (128 * ROW_B)             // 18432 B
#define STAGE_B  (4 * TILE_B)              // 73728 B
#define SM_TOTAL (2 * STAGE_B)             // 147456 B

__global__ void __launch_bounds__(256, 1)
gemm_s8(const int8_t* __restrict__ A1, const int8_t* __restrict__ A2q,
        const int8_t* __restrict__ B1, const int8_t* __restrict__ B2q,
        float* __restrict__ C,
        const unsigned* __restrict__ maxA, const unsigned* __restrict__ maxB)
{
    extern __shared__ __align__(16) char smem[];
    const uint32_t sb = smem_u32(smem);
    const int tid  = threadIdx.x;
    const int wid  = tid >> 5, lane = tid & 31;
    const int wm   = wid & 1;              // 64-row m group
    const int wn   = wid >> 1;             // 32-col n group
    const int n0 = blockIdx.x * 128, b = blockIdx.y;

    const int8_t* tb[4] = {
        A1  + (size_t)n0 * NNODE, A2q + (size_t)n0 * NNODE,
        B1  + (size_t)b * NFEAT * NNODE, B2q + (size_t)b * NFEAT * NNODE };

    // cp.async plan: 4 tiles x 128 rows x 8 chunks(16B) = 4096 chunks / 256 thr.
    // chunk c = j*256+tid: tile = j>>2, row = (j&3)*32 + (tid>>3), col16 = tid&7.
    const int c16   = (tid & 7) * 16;
    const int rbase = tid >> 3;

    // ldmatrix lane addresses (byte offsets within a stage)
    const uint32_t offA = (uint32_t)(wm * 64 + (lane & 15)) * ROW_B + (lane >> 4) * 16;
    const uint32_t offB = (uint32_t)(wn * 32 + (lane & 7)) * ROW_B + ((lane >> 3) & 1) * 16;

    int p1[4][4][4], p2[4][4][4];
    #pragma unroll
    for (int mi = 0; mi < 4; mi++)
        #pragma unroll
        for (int ni = 0; ni < 4; ni++)
            #pragma unroll
            for (int e = 0; e < 4; e++) { p1[mi][ni][e] = 0; p2[mi][ni][e] = 0; }

    // preload stage 0
    #pragma unroll
    for (int j = 0; j < 16; j++) {
        const int row = (j & 3) * 32 + rbase;
        CP16(sb + (j >> 2) * TILE_B + row * ROW_B + c16,
             tb[j >> 2] + (size_t)row * NNODE + c16);
    }
    CP_COMMIT();

    for (int i = 0; i < NSTAGE; i++) {
        const int buf = i & 1;
        if (i < NSTAGE - 1) {
            const uint32_t dbase = sb + (buf ^ 1) * STAGE_B;
            const int koff = (i + 1) * KC;
            #pragma unroll
            for (int j = 0; j < 16; j++) {
                const int row = (j & 3) * 32 + rbase;
                CP16(dbase + (j >> 2) * TILE_B + row * ROW_B + c16,
                     tb[j >> 2] + (size_t)row * NNODE + koff + c16);
            }
            CP_COMMIT();
            CP_WAIT1();
        } else {
            CP_WAIT0();
        }
        __syncthreads();

        const uint32_t s = sb + buf * STAGE_B;
        #pragma unroll
        for (int ks = 0; ks < 4; ks++) {           // 4 x k32 per stage
            uint32_t a1f[4][4], a2f[4][4];
            #pragma unroll
            for (int mi = 0; mi < 4; mi++) {
                const uint32_t a = s + offA + mi * (16 * ROW_B) + ks * 32;
                LDSM4(a1f[mi], a);
                LDSM4(a2f[mi], a + TILE_B);
            }
            #pragma unroll
            for (int ni = 0; ni < 4; ni++) {
                uint32_t b1f[2], b2f[2];
                const uint32_t a = s + 2 * TILE_B + offB + ni * (8 * ROW_B) + ks * 32;
                LDSM2(b1f, a);
                LDSM2(b2f, a + TILE_B);
                #pragma unroll
                for (int mi = 0; mi < 4; mi++) {
                    MMA_S8(p1[mi][ni], a1f[mi], b1f);
                    MMA_S8(p2[mi][ni], a1f[mi], b2f);
                    MMA_S8(p2[mi][ni], a2f[mi], b1f);
                }
            }
        }
        __syncthreads();
    }

    // epilogue: C = s1*P1 + s2*P2
    const float mA = __uint_as_float(*maxA), mB = __uint_as_float(*maxB);
    const float s1 = (mA * mB) * (1.f / 16129.f);   // /127^2
    const float s2 = s1 * (1.f / 256.f);
    const int mrow = wm * 64 + (lane >> 2);
    const int ncol = wn * 32 + (lane & 3) * 2;
    float* Cb = C + ((size_t)b * NNODE + n0) * NFEAT;
    #pragma unroll
    for (int mi = 0; mi < 4; mi++) {
        #pragma unroll
        for (int ni = 0; ni < 4; ni++) {
            float* q0 = Cb + (size_t)(mrow + mi * 16) * NFEAT + ncol + ni * 8;
            float* q1 = q0 + 8 * NFEAT;
            *(float2*)q0 = make_float2(s1 * (float)p1[mi][ni][0] + s2 * (float)p2[mi][ni][0],
                                       s1 * (float)p1[mi][ni][1] + s2 * (float)p2[mi][ni][1]);
            *(float2*)q1 = make_float2(s1 * (float)p1[mi][ni][2] + s2 * (float)p2[mi][ni][2],
                                       s1 * (float)p1[mi][ni][3] + s2 * (float)p2[mi][ni][3]);
        }
    }
}

// ---------------------------------------------------------------------------
// K2: fused MLP; writes fp32 transposed output + records block abs-max.
// A2T[b][w][n] = relu(T[row][:] @ W1 + b1) @ W2 , row = b*4096+n
// ---------------------------------------------------------------------------
__global__ void __launch_bounds__(256, 4)
mlp_fused(const float* __restrict__ T,
          const float* __restrict__ W1, const float* __restrict__ b1,
          const float* __restrict__ W2,
          float* __restrict__ A2T, unsigned* __restrict__ mx)
{
    __shared__ float ts[8][NFEAT];
    __shared__ float hs[8][NHID];
    __shared__ float os[8][NFEAT];
    __shared__ float red[8];

    const int tid = threadIdx.x;
    const size_t row0 = (size_t)blockIdx.x * 8;
    const int b     = (int)(row0 >> 12);
    const int nbase = (int)(row0 & 4095);

    ((float4*)&ts[0][0])[tid] = ((const float4*)(T + row0 * NFEAT))[tid];
    __syncthreads();

    // stage 1: thread j == tid computes h[r][j]
    float acc[8];
    const float bias = b1[tid];
    #pragma unroll
    for (int r = 0; r < 8; r++) acc[r] = bias;
    #pragma unroll 4
    for (int i = 0; i < NFEAT; i++) {
        const float w1 = W1[(size_t)i * NHID + tid];
        #pragma unroll
        for (int r = 0; r < 8; r++) acc[r] = fmaf(ts[r][i], w1, acc[r]);
    }
    #pragma unroll
    for (int r = 0; r < 8; r++) hs[r][tid] = fmaxf(acc[r], 0.f);
    __syncthreads();

    // stage 2
    const int w  = tid & 127;
    const int rb = tid >> 7;
    float o0 = 0.f, o1 = 0.f, o2 = 0.f, o3 = 0.f;
    #pragma unroll 4
    for (int j = 0; j < NHID; j++) {
        const float w2 = W2[(size_t)j * NFEAT + w];
        o0 = fmaf(hs[rb + 0][j], w2, o0);
        o1 = fmaf(hs[rb + 2][j], w2, o1);
        o2 = fmaf(hs[rb + 4][j], w2, o2);
        o3 = fmaf(hs[rb + 6][j], w2, o3);
    }
    os[rb + 0][w] = o0; os[rb + 2][w] = o1;
    os[rb + 4][w] = o2; os[rb + 6][w] = o3;

    // local abs-max over this thread's 4 outputs
    float lm = fmaxf(fmaxf(fabsf(o0), fabsf(o1)), fmaxf(fabsf(o2), fabsf(o3)));
    #pragma unroll
    for (int o = 16; o > 0; o >>= 1) lm = fmaxf(lm, __shfl_xor_sync(0xFFFFFFFFu, lm, o));
    if ((tid & 31) == 0) red[tid >> 5] = lm;
    __syncthreads();

    // transposed fp32 store: thread -> (w2, 4 consecutive n)
    const int w2 = tid & 127;
    const int ng = tid >> 7;                // 0 or 1 -> n offset 0 / 4
    float4 v = make_float4(os[ng * 4 + 0][w2], os[ng * 4 + 1][w2],
                           os[ng * 4 + 2][w2], os[ng * 4 + 3][w2]);
    *(float4*)(A2T + ((size_t)b * NFEAT + w2) * NNODE + nbase + ng * 4) = v;

    if (tid == 0) {
        float bmax = red[0];
        #pragma unroll
        for (int i = 1; i < 8; i++) bmax = fmaxf(bmax, red[i]);
        atomicMax(mx, __float_as_uint(bmax));
    }
}

// ---------------------------------------------------------------------------
// K4: out = log_softmax(O + b2). One warp per row.
// ---------------------------------------------------------------------------
__global__ void __launch_bounds__(256)
logsoftmax_k(const float* __restrict__ O,
             const float* __restrict__ b2,
             float* __restrict__ out)
{
    const int lane = threadIdx.x & 31;
    const size_t row = ((size_t)blockIdx.x * blockDim.x + threadIdx.x) >> 5;

    const float4 t  = ((const float4*)(O + row * NFEAT))[lane];
    const float4 bb = ((const float4*)b2)[lane];
    float v0 = t.x + bb.x, v1 = t.y + bb.y, v2 = t.z + bb.z, v3 = t.w + bb.w;

    float m = fmaxf(fmaxf(v0, v1), fmaxf(v2, v3));
    #pragma unroll
    for (int off = 16; off > 0; off >>= 1)
        m = fmaxf(m, __shfl_xor_sync(0xFFFFFFFFu, m, off));

    float s = expf(v0 - m) + expf(v1 - m) + expf(v2 - m) + expf(v3 - m);
    #pragma unroll
    for (int off = 16; off > 0; off >>= 1)
        s += __shfl_xor_sync(0xFFFFFFFFu, s, off);

    const float lse = m + logf(s);
    float4 o;
    o.x = v0 - lse; o.y = v1 - lse; o.z = v2 - lse; o.w = v3 - lse;
    ((float4*)(out + row * NFEAT))[lane] = o;
}

// ---------------------------------------------------------------------------
// Launch sequence
// ---------------------------------------------------------------------------
extern "C" void kernel_launch(void* const* d_in, const int* in_sizes, int n_in,
                              void* d_out, int out_size)
{
    const float* x   = (const float*)d_in[0];
    const float* adj = (const float*)d_in[1];
    const float* W1  = (const float*)d_in[2];
    const float* b1  = (const float*)d_in[3];
    const float* W2  = (const float*)d_in[4];
    const float* b2  = (const float*)d_in[5];
    float* out = (float*)d_out;

    int8_t *pA1, *pA2, *pB1, *pB2; float *pT, *pM; unsigned* pS;
    cudaGetSymbolAddress((void**)&pA1, g_A1);
    cudaGetSymbolAddress((void**)&pA2, g_A2q);
    cudaGetSymbolAddress((void**)&pB1, g_B1);
    cudaGetSymbolAddress((void**)&pB2, g_B2q);
    cudaGetSymbolAddress((void**)&pT,  g_T);
    cudaGetSymbolAddress((void**)&pM,  g_A2T);
    cudaGetSymbolAddress((void**)&pS,  g_scal);

    cudaFuncSetAttribute(gemm_s8, cudaFuncAttributeMaxDynamicSharedMemorySize, SM_TOTAL);

    const size_t nadj = (size_t)NNODE * NNODE;              // 16.8M
    const size_t nx   = (size_t)BATCH * NNODE * NFEAT;      // 33.5M
    const dim3 ggrid(NNODE / 128, BATCH);                   // 32 x 64
    const int  nrows = BATCH * NNODE;                       // 262144

    // scales
    zero_scal<<<1, 1>>>(pS);
    rmax4<<<2048, 256>>>((const float4*)adj, (int)(nadj / 4), pS + 0);
    rmax4<<<2048, 256>>>((const float4*)x,   (int)(nx / 4),   pS + 1);

    // quantize inputs
    quant_pt<<<(unsigned)(nadj / (256 * 4)), 256>>>(adj, pA1, pA2, pS + 0);
    quant_xT<<<dim3(NNODE / 32, NFEAT / 32, BATCH), dim3(32, 8)>>>(x, pB1, pB2, pS + 1);

    // K1: T = adj @ x
    gemm_s8<<<ggrid, 256, SM_TOTAL>>>(pA1, pA2, pB1, pB2, pT, pS + 0, pS + 1);
    // K2: A2T (fp32, transposed) + abs-max
    mlp_fused<<<nrows / 8, 256>>>(pT, W1, b1, W2, pM, pS + 2);
    // quantize MLP output (already [b][w][n])
    quant_pt<<<(unsigned)(nx / (256 * 4)), 256>>>(pM, pB1, pB2, pS + 2);
    // K3: O = adj @ A2  (reuse g_T)
    gemm_s8<<<ggrid, 256, SM_TOTAL>>>(pA1, pA2, pB1, pB2, pT, pS + 0, pS + 2);
    // K4
    logsoftmax_k<<<nrows / 8, 256>>>(pT, b2, out);

    (void)in_sizes; (void)n_in; (void)out_size;
}